// round 14
// baseline (speedup 1.0000x reference)
#include <cuda_runtime.h>
#include <cuda_fp16.h>
#include <math.h>
#include <stdint.h>

#define D_MODEL 1024
#define NUM_HEADS 16
#define D_HEAD 64
#define BATCH 2
#define SEQ 2048
#define BHN (BATCH*NUM_HEADS)
#define QER_RS 2056   // padded row stride (halves); keeps 16B alignment

// -------- scratch (static device memory; no runtime allocation) --------
__device__ float  g_q  [(size_t)BATCH*SEQ*D_MODEL];          // 16 MB fp32
__device__ __half g_k  [(size_t)BATCH*SEQ*D_MODEL];          // 8 MB fp16
__device__ __half g_vT [(size_t)BHN*D_HEAD*SEQ];             // 8 MB fp16, [bh][d][s]
__device__ __half g_qer[(size_t)BHN*SEQ*QER_RS + 128];       // ~269 MB fp16 (parity-shifted)
__device__ __half g_xh [(size_t)BATCH*SEQ*D_MODEL];          // 8 MB fp16 (x pre-converted)
__device__ __half g_wh [3][(size_t)D_MODEL*D_MODEL];         // 6 MB fp16 (Wq,Wk,Wv)

// ---------------- helpers ----------------
__device__ __forceinline__ void mma_f16(float& c0, float& c1, float& c2, float& c3,
                                        uint32_t a0, uint32_t a1, uint32_t a2, uint32_t a3,
                                        uint32_t b0, uint32_t b1) {
    asm volatile(
        "mma.sync.aligned.m16n8k16.row.col.f32.f16.f16.f32 "
        "{%0,%1,%2,%3}, {%4,%5,%6,%7}, {%8,%9}, {%0,%1,%2,%3};"
        : "+f"(c0), "+f"(c1), "+f"(c2), "+f"(c3)
        : "r"(a0), "r"(a1), "r"(a2), "r"(a3), "r"(b0), "r"(b1));
}
__device__ __forceinline__ void ldsm_x4(uint32_t& r0, uint32_t& r1, uint32_t& r2, uint32_t& r3,
                                        uint32_t saddr) {
    asm volatile("ldmatrix.sync.aligned.m8n8.x4.shared.b16 {%0,%1,%2,%3}, [%4];"
                 : "=r"(r0), "=r"(r1), "=r"(r2), "=r"(r3) : "r"(saddr));
}
__device__ __forceinline__ uint32_t pack_h2(float x, float y) {
    __half2 h = __floats2half2_rn(x, y);
    return *(uint32_t*)&h;
}
__device__ __forceinline__ uint32_t exp2_h2(float x, float y) {
    uint32_t u, r;
    asm("cvt.rn.f16x2.f32 %0, %1, %2;" : "=r"(u) : "f"(y), "f"(x));
    asm("ex2.approx.f16x2 %0, %1;" : "=r"(r) : "r"(u));
    return r;
}
__device__ __forceinline__ void cp_async16(uint32_t saddr, const void* g) {
    asm volatile("cp.async.cg.shared.global [%0], [%1], 16;" :: "r"(saddr), "l"(g));
}
#define CP_COMMIT() asm volatile("cp.async.commit_group;")
#define CP_WAIT0()  asm volatile("cp.async.wait_group 0;")
#define CP_WAIT2()  asm volatile("cp.async.wait_group 2;")

#define ONES_H2 0x3C003C00u
#define SCL 0.18033688011112042f   // 0.125 * log2(e)

#define HP 40
// qkv: 4-stage pipeline
#define QKV_SMEM_BYTES (4*128*HP*2*2)    // 81920 B
// qer: 2-stage (register-staged loader)
#define QER_SMEM_BYTES (2*128*HP*2*2)    // 40960 B

// ============================================================
// Kernel 0: convert x, Wq, Wk, Wv to fp16 once.
// ============================================================
__global__ __launch_bounds__(256)
void cvt_inputs_kernel(const float* __restrict__ x,
                       const float* __restrict__ Wq,
                       const float* __restrict__ Wk,
                       const float* __restrict__ Wv)
{
    const size_t XN = (size_t)BATCH*SEQ*D_MODEL;
    const size_t WN = (size_t)D_MODEL*D_MODEL;
    size_t i = ((size_t)blockIdx.x * blockDim.x + threadIdx.x) * 4;
    const float* src; __half* dst; size_t off;
    if (i < XN)              { src = x;  dst = g_xh;    off = i; }
    else if (i < XN + WN)    { src = Wq; dst = g_wh[0]; off = i - XN; }
    else if (i < XN + 2*WN)  { src = Wk; dst = g_wh[1]; off = i - XN - WN; }
    else if (i < XN + 3*WN)  { src = Wv; dst = g_wh[2]; off = i - XN - 2*WN; }
    else return;
    float4 v = *(const float4*)(src + off);
    *(uint32_t*)(dst + off)     = pack_h2(v.x, v.y);
    *(uint32_t*)(dst + off + 2) = pack_h2(v.z, v.w);
}

// ============================================================
// Kernel 1: Q/K/V projection. 4-stage cp.async pipeline (wait_group 2).
// ============================================================
__global__ __launch_bounds__(256, 2)
void qkv_tc_kernel(const float* __restrict__ bq,
                   const float* __restrict__ bk,
                   const float* __restrict__ bv)
{
    const __half* Wh = g_wh[blockIdx.z];
    const float* bias = (blockIdx.z == 0) ? bq : (blockIdx.z == 1) ? bk : bv;

    extern __shared__ __half smh[];
    __half* As = smh;                 // [4][128][HP]
    __half* Bs = smh + 4*128*HP;      // [4][128][HP]
    const uint32_t As_u = (uint32_t)__cvta_generic_to_shared(As);
    const uint32_t Bs_u = (uint32_t)__cvta_generic_to_shared(Bs);

    const int m0 = blockIdx.y * 128;
    const int n0 = blockIdx.x * 128;
    const int tid = threadIdx.x;
    const int wid = tid >> 5;
    const int lane = tid & 31;
    const int gid = lane >> 2;
    const int tig = lane & 3;
    const int wm = wid >> 2;
    const int wn = wid & 3;

    const int lmA_row = (lane & 7) + ((lane >> 3) & 1) * 8;
    const int lmA_kof = ((lane >> 4) & 1) * 8;
    const int lmB_row = (lane & 7) + ((lane >> 4) & 1) * 8;
    const int lmB_kof = ((lane >> 3) & 1) * 8;

    const __half* Ag = g_xh + (size_t)m0 * D_MODEL;
    const __half* Bg = Wh + (size_t)n0 * D_MODEL;

    // loader: 512 16B-chunks per array per k-chunk; 2 per thread per array
    const int ci0 = tid * 2, ci1 = tid * 2 + 1;
    const int ar0 = ci0 >> 2, ao0 = (ci0 & 3) * 8;   // halves offset within 32
    const int ar1 = ci1 >> 2, ao1 = (ci1 & 3) * 8;

    float c[4][4][4];
#pragma unroll
    for (int mt = 0; mt < 4; mt++)
#pragma unroll
        for (int nt = 0; nt < 4; nt++)
#pragma unroll
            for (int r = 0; r < 4; r++) c[mt][nt][r] = 0.f;

    const int NCH = D_MODEL / 32;   // 32 chunks

    // prologue: issue chunks 0..2 into stages 0..2
#pragma unroll
    for (int p = 0; p < 3; p++) {
        const uint32_t soff = (uint32_t)(p * 128 * HP * 2);
        const int k0 = p * 32;
        cp_async16(As_u + soff + (ar0*HP + ao0)*2, Ag + (size_t)ar0 * D_MODEL + k0 + ao0);
        cp_async16(As_u + soff + (ar1*HP + ao1)*2, Ag + (size_t)ar1 * D_MODEL + k0 + ao1);
        cp_async16(Bs_u + soff + (ar0*HP + ao0)*2, Bg + (size_t)ar0 * D_MODEL + k0 + ao0);
        cp_async16(Bs_u + soff + (ar1*HP + ao1)*2, Bg + (size_t)ar1 * D_MODEL + k0 + ao1);
        CP_COMMIT();
    }

    for (int i = 0; i < NCH; i++) {
        CP_WAIT2();          // chunk i complete (<=2 groups pending)
        __syncthreads();     // all warps' copies visible; stage (i+3)&3 free

        if (i + 3 < NCH) {
            const int st = (i + 3) & 3;
            const uint32_t soff = (uint32_t)(st * 128 * HP * 2);
            const int k0 = (i + 3) * 32;
            cp_async16(As_u + soff + (ar0*HP + ao0)*2, Ag + (size_t)ar0 * D_MODEL + k0 + ao0);
            cp_async16(As_u + soff + (ar1*HP + ao1)*2, Ag + (size_t)ar1 * D_MODEL + k0 + ao1);
            cp_async16(Bs_u + soff + (ar0*HP + ao0)*2, Bg + (size_t)ar0 * D_MODEL + k0 + ao0);
            cp_async16(Bs_u + soff + (ar1*HP + ao1)*2, Bg + (size_t)ar1 * D_MODEL + k0 + ao1);
        }
        CP_COMMIT();

        const int buf = i & 3;
#pragma unroll
        for (int ks = 0; ks < 2; ks++) {
            const int kk = ks * 16;
            uint32_t a[4][4];
#pragma unroll
            for (int mt = 0; mt < 4; mt++) {
                const uint32_t addr = As_u +
                    2u * (uint32_t)((buf*128 + wm*64 + mt*16 + lmA_row) * HP + kk + lmA_kof);
                ldsm_x4(a[mt][0], a[mt][1], a[mt][2], a[mt][3], addr);
            }
#pragma unroll
            for (int ntp = 0; ntp < 2; ntp++) {
                uint32_t b00, b01, b10, b11;
                const uint32_t addr = Bs_u +
                    2u * (uint32_t)((buf*128 + wn*32 + ntp*16 + lmB_row) * HP + kk + lmB_kof);
                ldsm_x4(b00, b01, b10, b11, addr);
#pragma unroll
                for (int mt = 0; mt < 4; mt++) {
                    mma_f16(c[mt][2*ntp][0], c[mt][2*ntp][1], c[mt][2*ntp][2], c[mt][2*ntp][3],
                            a[mt][0], a[mt][1], a[mt][2], a[mt][3], b00, b01);
                    mma_f16(c[mt][2*ntp+1][0], c[mt][2*ntp+1][1], c[mt][2*ntp+1][2], c[mt][2*ntp+1][3],
                            a[mt][0], a[mt][1], a[mt][2], a[mt][3], b10, b11);
                }
            }
        }
    }

    if (blockIdx.z == 0) {
#pragma unroll
        for (int nt = 0; nt < 4; nt++) {
            const int col = n0 + wn*32 + nt*8 + 2*tig;
            const float2 bb = *(const float2*)(bias + col);
#pragma unroll
            for (int mt = 0; mt < 4; mt++) {
                const int row = m0 + wm*64 + mt*16 + gid;
                *(float2*)(g_q + (size_t)row * D_MODEL + col) =
                    make_float2(c[mt][nt][0] + bb.x, c[mt][nt][1] + bb.y);
                *(float2*)(g_q + (size_t)(row + 8) * D_MODEL + col) =
                    make_float2(c[mt][nt][2] + bb.x, c[mt][nt][3] + bb.y);
            }
        }
    } else if (blockIdx.z == 1) {
#pragma unroll
        for (int nt = 0; nt < 4; nt++) {
            const int col = n0 + wn*32 + nt*8 + 2*tig;
            const float2 bb = *(const float2*)(bias + col);
#pragma unroll
            for (int mt = 0; mt < 4; mt++) {
                const int row = m0 + wm*64 + mt*16 + gid;
                *(__half2*)(g_k + (size_t)row * D_MODEL + col) =
                    __floats2half2_rn(c[mt][nt][0] + bb.x, c[mt][nt][1] + bb.y);
                *(__half2*)(g_k + (size_t)(row + 8) * D_MODEL + col) =
                    __floats2half2_rn(c[mt][nt][2] + bb.x, c[mt][nt][3] + bb.y);
            }
        }
    } else {
#pragma unroll
        for (int nt = 0; nt < 4; nt++) {
            const int col = n0 + wn*32 + nt*8 + 2*tig;
            const float2 bb = *(const float2*)(bias + col);
            const int hh = col >> 6;
            const int d0 = col & 63;
#pragma unroll
            for (int mt = 0; mt < 4; mt++) {
                const int row = m0 + wm*64 + mt*16 + gid;
                const int bidx = row >> 11;
                const int sidx = row & 2047;
                __half* base = g_vT + ((size_t)(bidx*NUM_HEADS + hh) * D_HEAD + d0) * SEQ;
                base[sidx]            = __float2half(c[mt][nt][0] + bb.x);
                base[SEQ + sidx]      = __float2half(c[mt][nt][1] + bb.y);
                base[sidx + 8]        = __float2half(c[mt][nt][2] + bb.x);
                base[SEQ + sidx + 8]  = __float2half(c[mt][nt][3] + bb.y);
            }
        }
    }
}

// ============================================================
// Kernel 2 (fp16 tensor core): QEr stored parity-shifted.
// ============================================================
__global__ __launch_bounds__(256, 2)
void qer_tc_kernel(const float* __restrict__ Er)
{
    const int bh = blockIdx.z;
    const int b = bh >> 4, h = bh & 15;
    const int j0 = blockIdx.x * 128;
    const int s0 = blockIdx.y * 128;
    if (s0 + j0 + 254 < SEQ - 1) return;

    extern __shared__ __half smh[];
    __half* As = smh;
    __half* Bs = smh + 2*128*HP;
    const uint32_t As_u = (uint32_t)__cvta_generic_to_shared(As);
    const uint32_t Bs_u = (uint32_t)__cvta_generic_to_shared(Bs);

    const int tid = threadIdx.x;
    const int wid = tid >> 5;
    const int lane = tid & 31;
    const int gid = lane >> 2;
    const int tig = lane & 3;
    const int wm = wid >> 2;
    const int wn = wid & 3;

    const int lmA_row = (lane & 7) + ((lane >> 3) & 1) * 8;
    const int lmA_kof = ((lane >> 4) & 1) * 8;
    const int lmB_row = (lane & 7) + ((lane >> 4) & 1) * 8;
    const int lmB_kof = ((lane >> 3) & 1) * 8;

    const float* Ag = g_q + ((size_t)b * SEQ + s0) * D_MODEL + (size_t)h * D_HEAD;
    const float* Bg = Er + (size_t)j0 * D_HEAD;

    float c[4][4][4];
#pragma unroll
    for (int mt = 0; mt < 4; mt++)
#pragma unroll
        for (int nt = 0; nt < 4; nt++)
#pragma unroll
            for (int r = 0; r < 4; r++) c[mt][nt][r] = 0.f;

    const int lrow = tid >> 3;
    const int lc4  = (tid & 7) * 4;

    float4 pa[4], pb[4];
#pragma unroll
    for (int i = 0; i < 4; i++) {
        pa[i] = *(const float4*)(Ag + (size_t)(lrow + i*32) * D_MODEL + lc4);
        pb[i] = *(const float4*)(Bg + (size_t)(lrow + i*32) * D_HEAD + lc4);
    }
#pragma unroll
    for (int i = 0; i < 4; i++) {
        __half* da = As + (lrow + i*32) * HP + lc4;
        *(uint32_t*)da       = pack_h2(pa[i].x, pa[i].y);
        *(uint32_t*)(da + 2) = pack_h2(pa[i].z, pa[i].w);
        __half* db = Bs + (lrow + i*32) * HP + lc4;
        *(uint32_t*)db       = pack_h2(pb[i].x, pb[i].y);
        *(uint32_t*)(db + 2) = pack_h2(pb[i].z, pb[i].w);
    }
    __syncthreads();

    for (int k0 = 0; k0 < D_HEAD; k0 += 32) {
        const int buf = (k0 >> 5) & 1;
        const bool has_next = (k0 + 32) < D_HEAD;
        if (has_next) {
#pragma unroll
            for (int i = 0; i < 4; i++) {
                pa[i] = *(const float4*)(Ag + (size_t)(lrow + i*32) * D_MODEL + k0 + 32 + lc4);
                pb[i] = *(const float4*)(Bg + (size_t)(lrow + i*32) * D_HEAD + k0 + 32 + lc4);
            }
        }
#pragma unroll
        for (int ks = 0; ks < 2; ks++) {
            const int kk = ks * 16;
            uint32_t a[4][4];
#pragma unroll
            for (int mt = 0; mt < 4; mt++) {
                const uint32_t addr = As_u +
                    2u * (uint32_t)((buf*128 + wm*64 + mt*16 + lmA_row) * HP + kk + lmA_kof);
                ldsm_x4(a[mt][0], a[mt][1], a[mt][2], a[mt][3], addr);
            }
#pragma unroll
            for (int ntp = 0; ntp < 2; ntp++) {
                uint32_t b00, b01, b10, b11;
                const uint32_t addr = Bs_u +
                    2u * (uint32_t)((buf*128 + wn*32 + ntp*16 + lmB_row) * HP + kk + lmB_kof);
                ldsm_x4(b00, b01, b10, b11, addr);
#pragma unroll
                for (int mt = 0; mt < 4; mt++) {
                    mma_f16(c[mt][2*ntp][0], c[mt][2*ntp][1], c[mt][2*ntp][2], c[mt][2*ntp][3],
                            a[mt][0], a[mt][1], a[mt][2], a[mt][3], b00, b01);
                    mma_f16(c[mt][2*ntp+1][0], c[mt][2*ntp+1][1], c[mt][2*ntp+1][2], c[mt][2*ntp+1][3],
                            a[mt][0], a[mt][1], a[mt][2], a[mt][3], b10, b11);
                }
            }
        }
        if (has_next) {
            const int nb = buf ^ 1;
#pragma unroll
            for (int i = 0; i < 4; i++) {
                __half* da = As + nb*128*HP + (lrow + i*32) * HP + lc4;
                *(uint32_t*)da       = pack_h2(pa[i].x, pa[i].y);
                *(uint32_t*)(da + 2) = pack_h2(pa[i].z, pa[i].w);
                __half* db = Bs + nb*128*HP + (lrow + i*32) * HP + lc4;
                *(uint32_t*)db       = pack_h2(pb[i].x, pb[i].y);
                *(uint32_t*)(db + 2) = pack_h2(pb[i].z, pb[i].w);
            }
            __syncthreads();
        }
    }

    __half* dst = g_qer + (size_t)bh * SEQ * QER_RS;
    const int delta = 1 - (gid & 1);
    if (delta == 0) {
#pragma unroll
        for (int nt = 0; nt < 4; nt++) {
            const int col = j0 + wn*32 + nt*8 + 2*tig;
#pragma unroll
            for (int mt = 0; mt < 4; mt++) {
                const int row = s0 + wm*64 + mt*16 + gid;
                *(__half2*)(dst + (size_t)row * QER_RS + col) =
                    __floats2half2_rn(c[mt][nt][0], c[mt][nt][1]);
                *(__half2*)(dst + (size_t)(row + 8) * QER_RS + col) =
                    __floats2half2_rn(c[mt][nt][2], c[mt][nt][3]);
            }
        }
    } else {
#pragma unroll
        for (int nt = 0; nt < 4; nt++) {
            const int col = j0 + wn*32 + nt*8 + 2*tig + 1;
#pragma unroll
            for (int mt = 0; mt < 4; mt++) {
                const int row = s0 + wm*64 + mt*16 + gid;
                dst[(size_t)row * QER_RS + col]         = __float2half(c[mt][nt][0]);
                dst[(size_t)row * QER_RS + col + 1]     = __float2half(c[mt][nt][1]);
                dst[(size_t)(row + 8) * QER_RS + col]     = __float2half(c[mt][nt][2]);
                dst[(size_t)(row + 8) * QER_RS + col + 1] = __float2half(c[mt][nt][3]);
            }
        }
    }
}

// ============================================================
// Kernel 3: fp16 flash attention (unchanged from round 13).
// ============================================================
#define AHP 72
#define ATT_SMEM_HALVES (2*64*AHP + 2*64*AHP)
#define ATT_SMEM_BYTES (ATT_SMEM_HALVES * 2)   // 36864 B

__global__ __launch_bounds__(256, 2)
void attn_tc_kernel(float* __restrict__ out)
{
    const int qt = gridDim.x - 1 - blockIdx.x;
    const int bh = blockIdx.y;
    const int b = bh >> 4, h = bh & 15;
    const int s0 = qt * 128;

    extern __shared__ __half smh[];
    __half* ks = smh;                    // [2][64][AHP]
    __half* vT = ks + 2*64*AHP;          // [2][64][AHP]

    const int tid = threadIdx.x;
    const int wid = tid >> 5;
    const int lane = tid & 31;
    const int gid = lane >> 2;
    const int tig = lane & 3;
    const int r0 = wid*16 + gid;
    const int r1 = r0 + 8;
    const int sg0 = s0 + r0;
    const int sg1 = s0 + r1;

    const int lmB_row = (lane & 7) + ((lane >> 4) & 1) * 8;
    const int lmB_kof = ((lane >> 3) & 1) * 8;

    const float*  qb  = g_q + ((size_t)b * SEQ + s0) * D_MODEL + (size_t)h * D_HEAD;
    const __half* kb  = g_k + (size_t)b * SEQ * D_MODEL + (size_t)h * D_HEAD;
    const __half* vtb = g_vT + (size_t)bh * D_HEAD * SEQ;
    const __half* qr0 = g_qer + (size_t)bh * SEQ * QER_RS + (size_t)sg0 * QER_RS;
    const __half* qr1 = g_qer + (size_t)bh * SEQ * QER_RS + (size_t)sg1 * QER_RS;
    const int delta = 1 - (sg0 & 1);
    const int sb0 = 2047 + 2*tig - sg0 + delta;   // even
    const int sb1 = sb0 - 8;                      // even

    uint32_t qf[4][4];
#pragma unroll
    for (int k4 = 0; k4 < 4; k4++) {
        const int cc = k4*16 + 2*tig;
        const float2 x0 = *(const float2*)(qb + (size_t)r0 * D_MODEL + cc);
        const float2 x1 = *(const float2*)(qb + (size_t)r1 * D_MODEL + cc);
        const float2 x2 = *(const float2*)(qb + (size_t)r0 * D_MODEL + cc + 8);
        const float2 x3 = *(const float2*)(qb + (size_t)r1 * D_MODEL + cc + 8);
        qf[k4][0] = pack_h2(x0.x, x0.y);
        qf[k4][1] = pack_h2(x1.x, x1.y);
        qf[k4][2] = pack_h2(x2.x, x2.y);
        qf[k4][3] = pack_h2(x3.x, x3.y);
    }

    const uint32_t ks_base = (uint32_t)__cvta_generic_to_shared(ks);
    const uint32_t vt_base = (uint32_t)__cvta_generic_to_shared(vT);
    const int ci0 = tid * 2;
    const int ci1 = tid * 2 + 1;
    const int krow0 = ci0 >> 3, ko0 = (ci0 & 7) * 8;
    const int krow1 = ci1 >> 3, ko1 = (ci1 & 7) * 8;

    float o[8][4];
#pragma unroll
    for (int nt = 0; nt < 8; nt++) { o[nt][0]=0.f; o[nt][1]=0.f; o[nt][2]=0.f; o[nt][3]=0.f; }
    float lacc[4] = {0.f, 0.f, 0.f, 0.f};
    float m0v = -1e30f, m1v = -1e30f;
    const int nkt = 2 * qt + 2;

    {
        cp_async16(ks_base + (krow0*AHP + ko0)*2, kb + (size_t)krow0 * D_MODEL + ko0);
        cp_async16(ks_base + (krow1*AHP + ko1)*2, kb + (size_t)krow1 * D_MODEL + ko1);
        cp_async16(vt_base + (krow0*AHP + ko0)*2, vtb + (size_t)krow0 * SEQ + ko0);
        cp_async16(vt_base + (krow1*AHP + ko1)*2, vtb + (size_t)krow1 * SEQ + ko1);
        CP_COMMIT();
    }

    float s_[8][4];
    {
#pragma unroll
        for (int nt = 0; nt < 8; nt++) {
            int ja = sb0 + nt*8;  ja = ja > 2048 ? 2048 : ja;
            int jc = sb1 + nt*8;  jc = jc > 2048 ? 2048 : jc;
            const uint32_t u0 = *(const uint32_t*)(qr0 + ja);
            const uint32_t u1 = *(const uint32_t*)(qr1 + jc);
            const float2 f0 = __half22float2(*(const __half2*)&u0);
            const float2 f1 = __half22float2(*(const __half2*)&u1);
            s_[nt][0] = f0.x; s_[nt][1] = f0.y;
            s_[nt][2] = f1.x; s_[nt][3] = f1.y;
        }
    }

    for (int kt = 0; kt < nkt; kt++) {
        const int t0 = kt * 64;
        const int buf = kt & 1;
        const bool masked = (kt >= 2*qt);

        CP_WAIT0();
        __syncthreads();

        if (kt + 1 < nkt) {
            const int t0n = t0 + 64;
            const int boff = (buf ^ 1) * 64 * AHP * 2;
            cp_async16(ks_base + boff + (krow0*AHP + ko0)*2, kb + (size_t)(t0n + krow0) * D_MODEL + ko0);
            cp_async16(ks_base + boff + (krow1*AHP + ko1)*2, kb + (size_t)(t0n + krow1) * D_MODEL + ko1);
            cp_async16(vt_base + boff + (krow0*AHP + ko0)*2, vtb + (size_t)krow0 * SEQ + t0n + ko0);
            cp_async16(vt_base + boff + (krow1*AHP + ko1)*2, vtb + (size_t)krow1 * SEQ + t0n + ko1);
        }
        CP_COMMIT();

        const uint32_t ksb_u = ks_base + (uint32_t)(buf * 64 * AHP * 2);
        const uint32_t vtf_u = vt_base + (uint32_t)(buf * 64 * AHP * 2);

#pragma unroll
        for (int k4 = 0; k4 < 4; k4++) {
            const int kk = k4 * 16;
#pragma unroll
            for (int ntp = 0; ntp < 4; ntp++) {
                uint32_t b00, b01, b10, b11;
                const uint32_t addr = ksb_u +
                    2u * (uint32_t)((ntp*16 + lmB_row) * AHP + kk + lmB_kof);
                ldsm_x4(b00, b01, b10, b11, addr);
                mma_f16(s_[2*ntp][0], s_[2*ntp][1], s_[2*ntp][2], s_[2*ntp][3],
                        qf[k4][0], qf[k4][1], qf[k4][2], qf[k4][3], b00, b01);
                mma_f16(s_[2*ntp+1][0], s_[2*ntp+1][1], s_[2*ntp+1][2], s_[2*ntp+1][3],
                        qf[k4][0], qf[k4][1], qf[k4][2], qf[k4][3], b10, b11);
            }
        }

        {
            float rmax = -1e30f;
            if (masked) {
#pragma unroll
                for (int nt = 0; nt < 8; nt++) {
                    int tc = t0 + nt*8 + 2*tig;
                    float v0 = s_[nt][0] * SCL;
                    float v1 = s_[nt][1] * SCL;
                    v0 = (tc     <= sg0) ? v0 : -1e30f;
                    v1 = (tc + 1 <= sg0) ? v1 : -1e30f;
                    s_[nt][0] = v0; s_[nt][1] = v1;
                    rmax = fmaxf(rmax, fmaxf(v0, v1));
                }
            } else {
#pragma unroll
                for (int nt = 0; nt < 8; nt++) {
                    float v0 = s_[nt][0] * SCL;
                    float v1 = s_[nt][1] * SCL;
                    s_[nt][0] = v0; s_[nt][1] = v1;
                    rmax = fmaxf(rmax, fmaxf(v0, v1));
                }
            }
            rmax = fmaxf(rmax, __shfl_xor_sync(0xffffffffu, rmax, 1));
            rmax = fmaxf(rmax, __shfl_xor_sync(0xffffffffu, rmax, 2));
            float mn = fmaxf(m0v, rmax);
            float alpha = exp2f(m0v - mn);
            m0v = mn;
            lacc[0] *= alpha;
#pragma unroll
            for (int nt = 0; nt < 8; nt++) {
                s_[nt][0] = __uint_as_float(exp2_h2(s_[nt][0] - mn, s_[nt][1] - mn));
                o[nt][0] *= alpha; o[nt][1] *= alpha;
            }
        }
        {
            float rmax = -1e30f;
            if (masked) {
#pragma unroll
                for (int nt = 0; nt < 8; nt++) {
                    int tc = t0 + nt*8 + 2*tig;
                    float v0 = s_[nt][2] * SCL;
                    float v1 = s_[nt][3] * SCL;
                    v0 = (tc     <= sg1) ? v0 : -1e30f;
                    v1 = (tc + 1 <= sg1) ? v1 : -1e30f;
                    s_[nt][2] = v0; s_[nt][3] = v1;
                    rmax = fmaxf(rmax, fmaxf(v0, v1));
                }
            } else {
#pragma unroll
                for (int nt = 0; nt < 8; nt++) {
                    float v0 = s_[nt][2] * SCL;
                    float v1 = s_[nt][3] * SCL;
                    s_[nt][2] = v0; s_[nt][3] = v1;
                    rmax = fmaxf(rmax, fmaxf(v0, v1));
                }
            }
            rmax = fmaxf(rmax, __shfl_xor_sync(0xffffffffu, rmax, 1));
            rmax = fmaxf(rmax, __shfl_xor_sync(0xffffffffu, rmax, 2));
            float mn = fmaxf(m1v, rmax);
            float alpha = exp2f(m1v - mn);
            m1v = mn;
            lacc[2] *= alpha;
#pragma unroll
            for (int nt = 0; nt < 8; nt++) {
                s_[nt][2] = __uint_as_float(exp2_h2(s_[nt][2] - mn, s_[nt][3] - mn));
                o[nt][2] *= alpha; o[nt][3] *= alpha;
            }
        }

#pragma unroll
        for (int k4 = 0; k4 < 4; k4++) {
            const int kk = k4 * 16;
            const uint32_t a0 = __float_as_uint(s_[2*k4][0]);
            const uint32_t a1 = __float_as_uint(s_[2*k4][2]);
            const uint32_t a2 = __float_as_uint(s_[2*k4+1][0]);
            const uint32_t a3 = __float_as_uint(s_[2*k4+1][2]);
#pragma unroll
            for (int ntp = 0; ntp < 4; ntp++) {
                uint32_t b00, b01, b10, b11;
                const uint32_t addr = vtf_u +
                    2u * (uint32_t)((ntp*16 + lmB_row) * AHP + kk + lmB_kof);
                ldsm_x4(b00, b01, b10, b11, addr);
                mma_f16(o[2*ntp][0], o[2*ntp][1], o[2*ntp][2], o[2*ntp][3],
                        a0, a1, a2, a3, b00, b01);
                mma_f16(o[2*ntp+1][0], o[2*ntp+1][1], o[2*ntp+1][2], o[2*ntp+1][3],
                        a0, a1, a2, a3, b10, b11);
            }
            mma_f16(lacc[0], lacc[1], lacc[2], lacc[3],
                    a0, a1, a2, a3, ONES_H2, ONES_H2);
        }

        {
            const int t0n = t0 + 64;
#pragma unroll
            for (int nt = 0; nt < 8; nt++) {
                int ja = sb0 + t0n + nt*8;  ja = ja > 2048 ? 2048 : ja;
                int jc = sb1 + t0n + nt*8;  jc = jc > 2048 ? 2048 : jc;
                const uint32_t u0 = *(const uint32_t*)(qr0 + ja);
                const uint32_t u1 = *(const uint32_t*)(qr1 + jc);
                const float2 f0 = __half22float2(*(const __half2*)&u0);
                const float2 f1 = __half22float2(*(const __half2*)&u1);
                s_[nt][0] = f0.x; s_[nt][1] = f0.y;
                s_[nt][2] = f1.x; s_[nt][3] = f1.y;
            }
        }
    }

    const float inv0 = 1.f / lacc[0];
    const float inv1 = 1.f / lacc[2];
    float* ob = out + (size_t)b * SEQ * D_MODEL + (size_t)h * D_HEAD;
#pragma unroll
    for (int nt = 0; nt < 8; nt++) {
        const int d = nt*8 + 2*tig;
        *(float2*)(ob + (size_t)sg0 * D_MODEL + d) = make_float2(o[nt][0]*inv0, o[nt][1]*inv0);
        *(float2*)(ob + (size_t)sg1 * D_MODEL + d) = make_float2(o[nt][2]*inv1, o[nt][3]*inv1);
    }
}

// ============================================================
// launcher
// ============================================================
extern "C" void kernel_launch(void* const* d_in, const int* in_sizes, int n_in,
                              void* d_out, int out_size)
{
    const float* x  = (const float*)d_in[0];
    const float* Wq = (const float*)d_in[1];
    const float* bq = (const float*)d_in[2];
    const float* Wk = (const float*)d_in[3];
    const float* bk = (const float*)d_in[4];
    const float* Wv = (const float*)d_in[5];
    const float* bv = (const float*)d_in[6];
    const float* Er = (const float*)d_in[7];
    float* out = (float*)d_out;

    cudaFuncSetAttribute(qkv_tc_kernel, cudaFuncAttributeMaxDynamicSharedMemorySize,
                         QKV_SMEM_BYTES);
    cudaFuncSetAttribute(qer_tc_kernel, cudaFuncAttributeMaxDynamicSharedMemorySize,
                         QER_SMEM_BYTES);
    cudaFuncSetAttribute(attn_tc_kernel, cudaFuncAttributeMaxDynamicSharedMemorySize,
                         ATT_SMEM_BYTES);

    // convert x and weights to fp16 once
    {
        const size_t total4 = ((size_t)BATCH*SEQ*D_MODEL + 3*(size_t)D_MODEL*D_MODEL) / 4;
        const int blocks = (int)((total4 + 255) / 256);
        cvt_inputs_kernel<<<blocks, 256>>>(x, Wq, Wk, Wv);
    }

    dim3 g1(D_MODEL / 128, (BATCH * SEQ) / 128, 3);
    qkv_tc_kernel<<<g1, 256, QKV_SMEM_BYTES>>>(bq, bk, bv);

    dim3 g2(SEQ / 128, SEQ / 128, BHN);
    qer_tc_kernel<<<g2, 256, QER_SMEM_BYTES>>>(Er);

    dim3 g3(SEQ / 128, BHN);
    attn_tc_kernel<<<g3, 256, ATT_SMEM_BYTES>>>(out);
}

// round 15
// speedup vs baseline: 1.1989x; 1.1989x over previous
#include <cuda_runtime.h>
#include <cuda_fp16.h>
#include <math.h>
#include <stdint.h>

#define D_MODEL 1024
#define NUM_HEADS 16
#define D_HEAD 64
#define BATCH 2
#define SEQ 2048
#define BHN (BATCH*NUM_HEADS)

// -------- scratch (static device memory; no runtime allocation) --------
__device__ float  g_q  [(size_t)BATCH*SEQ*D_MODEL];          // 16 MB fp32
__device__ __half g_k  [(size_t)BATCH*SEQ*D_MODEL];          // 8 MB fp16
__device__ __half g_vT [(size_t)BHN*D_HEAD*SEQ];             // 8 MB fp16, [bh][d][s]
__device__ __half g_erh[(size_t)2240*D_HEAD];                // Er fp16, rows 2048..2239 zero pad

// ---------------- helpers ----------------
__device__ __forceinline__ void mma_f16(float& c0, float& c1, float& c2, float& c3,
                                        uint32_t a0, uint32_t a1, uint32_t a2, uint32_t a3,
                                        uint32_t b0, uint32_t b1) {
    asm volatile(
        "mma.sync.aligned.m16n8k16.row.col.f32.f16.f16.f32 "
        "{%0,%1,%2,%3}, {%4,%5,%6,%7}, {%8,%9}, {%0,%1,%2,%3};"
        : "+f"(c0), "+f"(c1), "+f"(c2), "+f"(c3)
        : "r"(a0), "r"(a1), "r"(a2), "r"(a3), "r"(b0), "r"(b1));
}
__device__ __forceinline__ void ldsm_x4(uint32_t& r0, uint32_t& r1, uint32_t& r2, uint32_t& r3,
                                        uint32_t saddr) {
    asm volatile("ldmatrix.sync.aligned.m8n8.x4.shared.b16 {%0,%1,%2,%3}, [%4];"
                 : "=r"(r0), "=r"(r1), "=r"(r2), "=r"(r3) : "r"(saddr));
}
__device__ __forceinline__ uint32_t pack_h2(float x, float y) {
    __half2 h = __floats2half2_rn(x, y);
    return *(uint32_t*)&h;
}
__device__ __forceinline__ uint32_t exp2_h2(float x, float y) {
    uint32_t u, r;
    asm("cvt.rn.f16x2.f32 %0, %1, %2;" : "=r"(u) : "f"(y), "f"(x));
    asm("ex2.approx.f16x2 %0, %1;" : "=r"(r) : "r"(u));
    return r;
}
__device__ __forceinline__ void cp_async16(uint32_t saddr, const void* g) {
    asm volatile("cp.async.cg.shared.global [%0], [%1], 16;" :: "r"(saddr), "l"(g));
}
#define CP_COMMIT() asm volatile("cp.async.commit_group;")
#define CP_WAIT0()  asm volatile("cp.async.wait_group 0;")

#define ONES_H2 0x3C003C00u
#define SCL 0.18033688011112042f   // 0.125 * log2(e)

#define HP 40
#define GEMM_SMEM_BYTES (2*128*HP*2*2)   // 40960 B

// ============================================================
// Kernel 0: convert Er to fp16 (pad rows stay zero from init).
// ============================================================
__global__ __launch_bounds__(256)
void cvt_er_kernel(const float* __restrict__ Er)
{
    int i = (blockIdx.x * blockDim.x + threadIdx.x) * 4;
    if (i >= 2048 * D_HEAD) return;
    float4 v = *(const float4*)(Er + i);
    *(uint32_t*)(g_erh + i)     = pack_h2(v.x, v.y);
    *(uint32_t*)(g_erh + i + 2) = pack_h2(v.z, v.w);
}

// ============================================================
// Kernel 1 (fp16 tensor core): Q/K/V projection (round-13 form).
// ============================================================
__global__ __launch_bounds__(256, 2)
void qkv_tc_kernel(const float* __restrict__ x,
                   const float* __restrict__ Wq, const float* __restrict__ bq,
                   const float* __restrict__ Wk, const float* __restrict__ bk,
                   const float* __restrict__ Wv, const float* __restrict__ bv)
{
    const float* W; const float* bias;
    if (blockIdx.z == 0)      { W = Wq; bias = bq; }
    else if (blockIdx.z == 1) { W = Wk; bias = bk; }
    else                      { W = Wv; bias = bv; }

    extern __shared__ __half smh[];
    __half* As = smh;                // [2][128][HP]
    __half* Bs = smh + 2*128*HP;     // [2][128][HP]
    const uint32_t As_u = (uint32_t)__cvta_generic_to_shared(As);
    const uint32_t Bs_u = (uint32_t)__cvta_generic_to_shared(Bs);

    const int m0 = blockIdx.y * 128;
    const int n0 = blockIdx.x * 128;
    const int tid = threadIdx.x;
    const int wid = tid >> 5;
    const int lane = tid & 31;
    const int gid = lane >> 2;
    const int tig = lane & 3;
    const int wm = wid >> 2;
    const int wn = wid & 3;

    const int lmA_row = (lane & 7) + ((lane >> 3) & 1) * 8;
    const int lmA_kof = ((lane >> 4) & 1) * 8;
    const int lmB_row = (lane & 7) + ((lane >> 4) & 1) * 8;
    const int lmB_kof = ((lane >> 3) & 1) * 8;

    const float* Ag = x + (size_t)m0 * D_MODEL;
    const float* Bg = W + (size_t)n0 * D_MODEL;

    float c[4][4][4];
#pragma unroll
    for (int mt = 0; mt < 4; mt++)
#pragma unroll
        for (int nt = 0; nt < 4; nt++)
#pragma unroll
            for (int r = 0; r < 4; r++) c[mt][nt][r] = 0.f;

    const int lrow = tid >> 3;
    const int lc4  = (tid & 7) * 4;

    float4 pa[4], pb[4];
#pragma unroll
    for (int i = 0; i < 4; i++) {
        pa[i] = *(const float4*)(Ag + (size_t)(lrow + i*32) * D_MODEL + lc4);
        pb[i] = *(const float4*)(Bg + (size_t)(lrow + i*32) * D_MODEL + lc4);
    }
#pragma unroll
    for (int i = 0; i < 4; i++) {
        __half* da = As + (lrow + i*32) * HP + lc4;
        *(uint32_t*)da       = pack_h2(pa[i].x, pa[i].y);
        *(uint32_t*)(da + 2) = pack_h2(pa[i].z, pa[i].w);
        __half* db = Bs + (lrow + i*32) * HP + lc4;
        *(uint32_t*)db       = pack_h2(pb[i].x, pb[i].y);
        *(uint32_t*)(db + 2) = pack_h2(pb[i].z, pb[i].w);
    }
    __syncthreads();

    for (int k0 = 0; k0 < D_MODEL; k0 += 32) {
        const int buf = (k0 >> 5) & 1;
        const bool has_next = (k0 + 32) < D_MODEL;
        if (has_next) {
#pragma unroll
            for (int i = 0; i < 4; i++) {
                pa[i] = *(const float4*)(Ag + (size_t)(lrow + i*32) * D_MODEL + k0 + 32 + lc4);
                pb[i] = *(const float4*)(Bg + (size_t)(lrow + i*32) * D_MODEL + k0 + 32 + lc4);
            }
        }
#pragma unroll
        for (int ks = 0; ks < 2; ks++) {
            const int kk = ks * 16;
            uint32_t a[4][4];
#pragma unroll
            for (int mt = 0; mt < 4; mt++) {
                const uint32_t addr = As_u +
                    2u * (uint32_t)((buf*128 + wm*64 + mt*16 + lmA_row) * HP + kk + lmA_kof);
                ldsm_x4(a[mt][0], a[mt][1], a[mt][2], a[mt][3], addr);
            }
#pragma unroll
            for (int ntp = 0; ntp < 2; ntp++) {
                uint32_t b00, b01, b10, b11;
                const uint32_t addr = Bs_u +
                    2u * (uint32_t)((buf*128 + wn*32 + ntp*16 + lmB_row) * HP + kk + lmB_kof);
                ldsm_x4(b00, b01, b10, b11, addr);
#pragma unroll
                for (int mt = 0; mt < 4; mt++) {
                    mma_f16(c[mt][2*ntp][0], c[mt][2*ntp][1], c[mt][2*ntp][2], c[mt][2*ntp][3],
                            a[mt][0], a[mt][1], a[mt][2], a[mt][3], b00, b01);
                    mma_f16(c[mt][2*ntp+1][0], c[mt][2*ntp+1][1], c[mt][2*ntp+1][2], c[mt][2*ntp+1][3],
                            a[mt][0], a[mt][1], a[mt][2], a[mt][3], b10, b11);
                }
            }
        }
        if (has_next) {
            const int nb = buf ^ 1;
#pragma unroll
            for (int i = 0; i < 4; i++) {
                __half* da = As + nb*128*HP + (lrow + i*32) * HP + lc4;
                *(uint32_t*)da       = pack_h2(pa[i].x, pa[i].y);
                *(uint32_t*)(da + 2) = pack_h2(pa[i].z, pa[i].w);
                __half* db = Bs + nb*128*HP + (lrow + i*32) * HP + lc4;
                *(uint32_t*)db       = pack_h2(pb[i].x, pb[i].y);
                *(uint32_t*)(db + 2) = pack_h2(pb[i].z, pb[i].w);
            }
            __syncthreads();
        }
    }

    if (blockIdx.z == 0) {
#pragma unroll
        for (int nt = 0; nt < 4; nt++) {
            const int col = n0 + wn*32 + nt*8 + 2*tig;
            const float2 bb = *(const float2*)(bias + col);
#pragma unroll
            for (int mt = 0; mt < 4; mt++) {
                const int row = m0 + wm*64 + mt*16 + gid;
                *(float2*)(g_q + (size_t)row * D_MODEL + col) =
                    make_float2(c[mt][nt][0] + bb.x, c[mt][nt][1] + bb.y);
                *(float2*)(g_q + (size_t)(row + 8) * D_MODEL + col) =
                    make_float2(c[mt][nt][2] + bb.x, c[mt][nt][3] + bb.y);
            }
        }
    } else if (blockIdx.z == 1) {
#pragma unroll
        for (int nt = 0; nt < 4; nt++) {
            const int col = n0 + wn*32 + nt*8 + 2*tig;
            const float2 bb = *(const float2*)(bias + col);
#pragma unroll
            for (int mt = 0; mt < 4; mt++) {
                const int row = m0 + wm*64 + mt*16 + gid;
                *(__half2*)(g_k + (size_t)row * D_MODEL + col) =
                    __floats2half2_rn(c[mt][nt][0] + bb.x, c[mt][nt][1] + bb.y);
                *(__half2*)(g_k + (size_t)(row + 8) * D_MODEL + col) =
                    __floats2half2_rn(c[mt][nt][2] + bb.x, c[mt][nt][3] + bb.y);
            }
        }
    } else {
#pragma unroll
        for (int nt = 0; nt < 4; nt++) {
            const int col = n0 + wn*32 + nt*8 + 2*tig;
            const float2 bb = *(const float2*)(bias + col);
            const int hh = col >> 6;
            const int d0 = col & 63;
#pragma unroll
            for (int mt = 0; mt < 4; mt++) {
                const int row = m0 + wm*64 + mt*16 + gid;
                const int bidx = row >> 11;
                const int sidx = row & 2047;
                __half* base = g_vT + ((size_t)(bidx*NUM_HEADS + hh) * D_HEAD + d0) * SEQ;
                base[sidx]            = __float2half(c[mt][nt][0] + bb.x);
                base[SEQ + sidx]      = __float2half(c[mt][nt][1] + bb.y);
                base[sidx + 8]        = __float2half(c[mt][nt][2] + bb.x);
                base[SEQ + sidx + 8]  = __float2half(c[mt][nt][3] + bb.y);
            }
        }
    }
}

// ============================================================
// Kernel 2: fused flash attention + inline rel-bias GEMM.
// Rel chunks computed per tile into a 192-wide skewed smem ring.
// ============================================================
#define AHP 72
#define RRS 200                         // rel ring row stride (halves); 4r+tig banks
#define SM_KS   0
#define SM_VT   (2*64*AHP)
#define SM_ER   (2*(2*64*AHP))
#define SM_REL  (SM_ER + 2*64*AHP)
#define ATT_SMEM_HALVES (SM_REL + 128*RRS)
#define ATT_SMEM_BYTES (ATT_SMEM_HALVES * 2)   // 106,496 B

__global__ __launch_bounds__(256, 2)
void attn_tc_kernel(float* __restrict__ out)
{
    const int qt = gridDim.x - 1 - blockIdx.x;
    const int bh = blockIdx.y;
    const int b = bh >> 4, h = bh & 15;
    const int s0 = qt * 128;
    const int ebase = 1920 - s0;          // Er row base for chunk 0

    extern __shared__ __half smh[];
    __half* rel = smh + SM_REL;           // [128][RRS]

    const int tid = threadIdx.x;
    const int wid = tid >> 5;
    const int lane = tid & 31;
    const int gid = lane >> 2;
    const int tig = lane & 3;
    const int r0 = wid*16 + gid;
    const int r1 = r0 + 8;
    const int sg0 = s0 + r0;
    const int sg1 = s0 + r1;

    const int lmB_row = (lane & 7) + ((lane >> 4) & 1) * 8;
    const int lmB_kof = ((lane >> 3) & 1) * 8;

    const float*  qb  = g_q + ((size_t)b * SEQ + s0) * D_MODEL + (size_t)h * D_HEAD;
    const __half* kb  = g_k + (size_t)b * SEQ * D_MODEL + (size_t)h * D_HEAD;
    const __half* vtb = g_vT + (size_t)bh * D_HEAD * SEQ;

    // Q fragments resident in registers
    uint32_t qf[4][4];
#pragma unroll
    for (int k4 = 0; k4 < 4; k4++) {
        const int cc = k4*16 + 2*tig;
        const float2 x0 = *(const float2*)(qb + (size_t)r0 * D_MODEL + cc);
        const float2 x1 = *(const float2*)(qb + (size_t)r1 * D_MODEL + cc);
        const float2 x2 = *(const float2*)(qb + (size_t)r0 * D_MODEL + cc + 8);
        const float2 x3 = *(const float2*)(qb + (size_t)r1 * D_MODEL + cc + 8);
        qf[k4][0] = pack_h2(x0.x, x0.y);
        qf[k4][1] = pack_h2(x1.x, x1.y);
        qf[k4][2] = pack_h2(x2.x, x2.y);
        qf[k4][3] = pack_h2(x3.x, x3.y);
    }

    const uint32_t ks_u = (uint32_t)__cvta_generic_to_shared(smh + SM_KS);
    const uint32_t vt_u = (uint32_t)__cvta_generic_to_shared(smh + SM_VT);
    const uint32_t er_u = (uint32_t)__cvta_generic_to_shared(smh + SM_ER);
    const int ci0 = tid * 2;
    const int ci1 = tid * 2 + 1;
    const int krow0 = ci0 >> 3, ko0 = (ci0 & 7) * 8;
    const int krow1 = ci1 >> 3, ko1 = (ci1 & 7) * 8;

    float o[8][4];
#pragma unroll
    for (int nt = 0; nt < 8; nt++) { o[nt][0]=0.f; o[nt][1]=0.f; o[nt][2]=0.f; o[nt][3]=0.f; }
    float lacc[4] = {0.f, 0.f, 0.f, 0.f};
    float m0v = -1e30f, m1v = -1e30f;
    const int nkt = 2 * qt + 2;
    const bool rodd = (r0 & 1);           // row parity (r1 same)

    // prologue: K/V tile0 + Er chunks 0,1
    {
        cp_async16(ks_u + (krow0*AHP + ko0)*2, kb + (size_t)krow0 * D_MODEL + ko0);
        cp_async16(ks_u + (krow1*AHP + ko1)*2, kb + (size_t)krow1 * D_MODEL + ko1);
        cp_async16(vt_u + (krow0*AHP + ko0)*2, vtb + (size_t)krow0 * SEQ + ko0);
        cp_async16(vt_u + (krow1*AHP + ko1)*2, vtb + (size_t)krow1 * SEQ + ko1);
#pragma unroll
        for (int cc = 0; cc < 2; cc++) {
            const uint32_t soff = (uint32_t)(cc * 64 * AHP * 2);
            const __half* esrc = g_erh + (size_t)(ebase + 64*cc) * D_HEAD;
            cp_async16(er_u + soff + (krow0*AHP + ko0)*2, esrc + (size_t)krow0 * D_HEAD + ko0);
            cp_async16(er_u + soff + (krow1*AHP + ko1)*2, esrc + (size_t)krow1 * D_HEAD + ko1);
        }
        CP_COMMIT();
        CP_WAIT0();
        __syncthreads();

        // compute rel chunks 0,1 into ring (skip t<0)
#pragma unroll
        for (int cc = 0; cc < 2; cc++) {
            const uint32_t erb = er_u + (uint32_t)(cc * 64 * AHP * 2);
#pragma unroll
            for (int ntp = 0; ntp < 4; ntp++) {
                float ra[4] = {0,0,0,0}, rb[4] = {0,0,0,0};
#pragma unroll
                for (int k4 = 0; k4 < 4; k4++) {
                    const int kk = k4 * 16;
                    uint32_t b00, b01, b10, b11;
                    ldsm_x4(b00, b01, b10, b11,
                            erb + 2u*(uint32_t)((ntp*16 + lmB_row)*AHP + kk + lmB_kof));
                    mma_f16(ra[0], ra[1], ra[2], ra[3],
                            qf[k4][0], qf[k4][1], qf[k4][2], qf[k4][3], b00, b01);
                    mma_f16(rb[0], rb[1], rb[2], rb[3],
                            qf[k4][0], qf[k4][1], qf[k4][2], qf[k4][3], b10, b11);
                }
                const int i0 = ntp*16 + 2*tig;
#pragma unroll
                for (int hh2 = 0; hh2 < 4; hh2++) {
                    const int rr = (hh2 & 1) ? r1 : r0;
                    const int ii = i0 + (hh2 >> 1) * 8;
                    const float v0 = (hh2 == 0) ? ra[0] : (hh2 == 1) ? ra[2] : (hh2 == 2) ? rb[0] : rb[2];
                    const float v1 = (hh2 == 0) ? ra[1] : (hh2 == 1) ? ra[3] : (hh2 == 2) ? rb[1] : rb[3];
                    const int tw = 64*cc + ii + rr - 127;
                    __half* rp = rel + rr * RRS;
                    if (!rodd) {                     // t odd: two scalar stores
                        if (tw >= 0)     rp[tw]     = __float2half(v0);
                        if (tw + 1 >= 0) rp[tw + 1] = __float2half(v1);
                    } else {                         // t even: aligned pair
                        if (tw >= 0) *(uint32_t*)(rp + tw) = pack_h2(v0, v1);
                    }
                }
            }
        }
        __syncthreads();                 // slot0 consumed by all before reuse
        // prefetch Er chunk 2 -> slot 0
        const __half* esrc = g_erh + (size_t)(ebase + 128) * D_HEAD;
        cp_async16(er_u + (krow0*AHP + ko0)*2, esrc + (size_t)krow0 * D_HEAD + ko0);
        cp_async16(er_u + (krow1*AHP + ko1)*2, esrc + (size_t)krow1 * D_HEAD + ko1);
        CP_COMMIT();
    }

    int rbase = 0;   // (64*kt) % 192

    for (int kt = 0; kt < nkt; kt++) {
        const int t0 = kt * 64;
        const int buf = kt & 1;
        const bool masked = (kt >= 2*qt);

        CP_WAIT0();
        __syncthreads();                 // K/V(kt), Er(kt+2) ready

        if (kt + 1 < nkt) {
            const int t0n = t0 + 64;
            const int boff = (buf ^ 1) * 64 * AHP * 2;
            cp_async16(ks_u + boff + (krow0*AHP + ko0)*2, kb + (size_t)(t0n + krow0) * D_MODEL + ko0);
            cp_async16(ks_u + boff + (krow1*AHP + ko1)*2, kb + (size_t)(t0n + krow1) * D_MODEL + ko1);
            cp_async16(vt_u + boff + (krow0*AHP + ko0)*2, vtb + (size_t)krow0 * SEQ + t0n + ko0);
            cp_async16(vt_u + boff + (krow1*AHP + ko1)*2, vtb + (size_t)krow1 * SEQ + t0n + ko1);
            // Er chunk kt+3 -> slot (kt+3)&1
            const uint32_t eoff = (uint32_t)(((kt + 3) & 1) * 64 * AHP * 2);
            const __half* esrc = g_erh + (size_t)(ebase + 64*(kt + 3)) * D_HEAD;
            cp_async16(er_u + eoff + (krow0*AHP + ko0)*2, esrc + (size_t)krow0 * D_HEAD + ko0);
            cp_async16(er_u + eoff + (krow1*AHP + ko1)*2, esrc + (size_t)krow1 * D_HEAD + ko1);
        }
        CP_COMMIT();

        // ---- rel chunk kt+2 from Er slot (kt&1) -> skewed ring ----
        {
            const uint32_t erb = er_u + (uint32_t)((kt & 1) * 64 * AHP * 2);
#pragma unroll
            for (int ntp = 0; ntp < 4; ntp++) {
                float ra[4] = {0,0,0,0}, rb[4] = {0,0,0,0};
#pragma unroll
                for (int k4 = 0; k4 < 4; k4++) {
                    const int kk = k4 * 16;
                    uint32_t b00, b01, b10, b11;
                    ldsm_x4(b00, b01, b10, b11,
                            erb + 2u*(uint32_t)((ntp*16 + lmB_row)*AHP + kk + lmB_kof));
                    mma_f16(ra[0], ra[1], ra[2], ra[3],
                            qf[k4][0], qf[k4][1], qf[k4][2], qf[k4][3], b00, b01);
                    mma_f16(rb[0], rb[1], rb[2], rb[3],
                            qf[k4][0], qf[k4][1], qf[k4][2], qf[k4][3], b10, b11);
                }
                const int i0 = ntp*16 + 2*tig;
#pragma unroll
                for (int hh2 = 0; hh2 < 4; hh2++) {
                    const int rr = (hh2 & 1) ? r1 : r0;
                    const int ii = i0 + (hh2 >> 1) * 8;
                    const float v0 = (hh2 == 0) ? ra[0] : (hh2 == 1) ? ra[2] : (hh2 == 2) ? rb[0] : rb[2];
                    const float v1 = (hh2 == 0) ? ra[1] : (hh2 == 1) ? ra[3] : (hh2 == 2) ? rb[1] : rb[3];
                    int idx = rbase + ii + rr + 1;
                    if (idx >= 192) idx -= 192;
                    __half* rp = rel + rr * RRS;
                    if (!rodd) {                     // idx odd: scalar pair with wrap
                        int idx2 = idx + 1; if (idx2 >= 192) idx2 = 0;
                        rp[idx]  = __float2half(v0);
                        rp[idx2] = __float2half(v1);
                    } else {                         // idx even, <=190: aligned pair
                        *(uint32_t*)(rp + idx) = pack_h2(v0, v1);
                    }
                }
            }
        }
        __syncthreads();                 // rel chunk kt+2 visible to all

        // ---- seed s_ from skewed ring (aligned u32) ----
        float s_[8][4];
        {
            const __half* rp0 = rel + r0 * RRS;
            const __half* rp1 = rel + r1 * RRS;
#pragma unroll
            for (int nt = 0; nt < 8; nt++) {
                const int ridx = rbase + nt*8 + 2*tig;   // <=190, even
                const uint32_t u0 = *(const uint32_t*)(rp0 + ridx);
                const uint32_t u1 = *(const uint32_t*)(rp1 + ridx);
                const float2 f0 = __half22float2(*(const __half2*)&u0);
                const float2 f1 = __half22float2(*(const __half2*)&u1);
                s_[nt][0] = f0.x; s_[nt][1] = f0.y;
                s_[nt][2] = f1.x; s_[nt][3] = f1.y;
            }
        }

        const uint32_t ksb_u = ks_u + (uint32_t)(buf * 64 * AHP * 2);
        const uint32_t vtf_u = vt_u + (uint32_t)(buf * 64 * AHP * 2);

        // S += Q K^T
#pragma unroll
        for (int k4 = 0; k4 < 4; k4++) {
            const int kk = k4 * 16;
#pragma unroll
            for (int ntp = 0; ntp < 4; ntp++) {
                uint32_t b00, b01, b10, b11;
                const uint32_t addr = ksb_u +
                    2u * (uint32_t)((ntp*16 + lmB_row) * AHP + kk + lmB_kof);
                ldsm_x4(b00, b01, b10, b11, addr);
                mma_f16(s_[2*ntp][0], s_[2*ntp][1], s_[2*ntp][2], s_[2*ntp][3],
                        qf[k4][0], qf[k4][1], qf[k4][2], qf[k4][3], b00, b01);
                mma_f16(s_[2*ntp+1][0], s_[2*ntp+1][1], s_[2*ntp+1][2], s_[2*ntp+1][3],
                        qf[k4][0], qf[k4][1], qf[k4][2], qf[k4][3], b10, b11);
            }
        }

        // ---- online softmax (log2 domain), row half 0 ----
        {
            float rmax = -1e30f;
            if (masked) {
#pragma unroll
                for (int nt = 0; nt < 8; nt++) {
                    int tc = t0 + nt*8 + 2*tig;
                    float v0 = s_[nt][0] * SCL;
                    float v1 = s_[nt][1] * SCL;
                    v0 = (tc     <= sg0) ? v0 : -1e30f;
                    v1 = (tc + 1 <= sg0) ? v1 : -1e30f;
                    s_[nt][0] = v0; s_[nt][1] = v1;
                    rmax = fmaxf(rmax, fmaxf(v0, v1));
                }
            } else {
#pragma unroll
                for (int nt = 0; nt < 8; nt++) {
                    float v0 = s_[nt][0] * SCL;
                    float v1 = s_[nt][1] * SCL;
                    s_[nt][0] = v0; s_[nt][1] = v1;
                    rmax = fmaxf(rmax, fmaxf(v0, v1));
                }
            }
            rmax = fmaxf(rmax, __shfl_xor_sync(0xffffffffu, rmax, 1));
            rmax = fmaxf(rmax, __shfl_xor_sync(0xffffffffu, rmax, 2));
            float mn = fmaxf(m0v, rmax);
            float alpha = exp2f(m0v - mn);
            m0v = mn;
            lacc[0] *= alpha;
#pragma unroll
            for (int nt = 0; nt < 8; nt++) {
                s_[nt][0] = __uint_as_float(exp2_h2(s_[nt][0] - mn, s_[nt][1] - mn));
                o[nt][0] *= alpha; o[nt][1] *= alpha;
            }
        }
        // ---- row half 1 ----
        {
            float rmax = -1e30f;
            if (masked) {
#pragma unroll
                for (int nt = 0; nt < 8; nt++) {
                    int tc = t0 + nt*8 + 2*tig;
                    float v0 = s_[nt][2] * SCL;
                    float v1 = s_[nt][3] * SCL;
                    v0 = (tc     <= sg1) ? v0 : -1e30f;
                    v1 = (tc + 1 <= sg1) ? v1 : -1e30f;
                    s_[nt][2] = v0; s_[nt][3] = v1;
                    rmax = fmaxf(rmax, fmaxf(v0, v1));
                }
            } else {
#pragma unroll
                for (int nt = 0; nt < 8; nt++) {
                    float v0 = s_[nt][2] * SCL;
                    float v1 = s_[nt][3] * SCL;
                    s_[nt][2] = v0; s_[nt][3] = v1;
                    rmax = fmaxf(rmax, fmaxf(v0, v1));
                }
            }
            rmax = fmaxf(rmax, __shfl_xor_sync(0xffffffffu, rmax, 1));
            rmax = fmaxf(rmax, __shfl_xor_sync(0xffffffffu, rmax, 2));
            float mn = fmaxf(m1v, rmax);
            float alpha = exp2f(m1v - mn);
            m1v = mn;
            lacc[2] *= alpha;
#pragma unroll
            for (int nt = 0; nt < 8; nt++) {
                s_[nt][2] = __uint_as_float(exp2_h2(s_[nt][2] - mn, s_[nt][3] - mn));
                o[nt][2] *= alpha; o[nt][3] *= alpha;
            }
        }

        // O += P V ; l += P 1
#pragma unroll
        for (int k4 = 0; k4 < 4; k4++) {
            const int kk = k4 * 16;
            const uint32_t a0 = __float_as_uint(s_[2*k4][0]);
            const uint32_t a1 = __float_as_uint(s_[2*k4][2]);
            const uint32_t a2 = __float_as_uint(s_[2*k4+1][0]);
            const uint32_t a3 = __float_as_uint(s_[2*k4+1][2]);
#pragma unroll
            for (int ntp = 0; ntp < 4; ntp++) {
                uint32_t b00, b01, b10, b11;
                const uint32_t addr = vtf_u +
                    2u * (uint32_t)((ntp*16 + lmB_row) * AHP + kk + lmB_kof);
                ldsm_x4(b00, b01, b10, b11, addr);
                mma_f16(o[2*ntp][0], o[2*ntp][1], o[2*ntp][2], o[2*ntp][3],
                        a0, a1, a2, a3, b00, b01);
                mma_f16(o[2*ntp+1][0], o[2*ntp+1][1], o[2*ntp+1][2], o[2*ntp+1][3],
                        a0, a1, a2, a3, b10, b11);
            }
            mma_f16(lacc[0], lacc[1], lacc[2], lacc[3],
                    a0, a1, a2, a3, ONES_H2, ONES_H2);
        }

        rbase += 64;
        if (rbase >= 192) rbase = 0;
    }

    const float inv0 = 1.f / lacc[0];
    const float inv1 = 1.f / lacc[2];
    float* ob = out + (size_t)b * SEQ * D_MODEL + (size_t)h * D_HEAD;
#pragma unroll
    for (int nt = 0; nt < 8; nt++) {
        const int d = nt*8 + 2*tig;
        *(float2*)(ob + (size_t)sg0 * D_MODEL + d) = make_float2(o[nt][0]*inv0, o[nt][1]*inv0);
        *(float2*)(ob + (size_t)sg1 * D_MODEL + d) = make_float2(o[nt][2]*inv1, o[nt][3]*inv1);
    }
}

// ============================================================
// launcher
// ============================================================
extern "C" void kernel_launch(void* const* d_in, const int* in_sizes, int n_in,
                              void* d_out, int out_size)
{
    const float* x  = (const float*)d_in[0];
    const float* Wq = (const float*)d_in[1];
    const float* bq = (const float*)d_in[2];
    const float* Wk = (const float*)d_in[3];
    const float* bk = (const float*)d_in[4];
    const float* Wv = (const float*)d_in[5];
    const float* bv = (const float*)d_in[6];
    const float* Er = (const float*)d_in[7];
    float* out = (float*)d_out;

    cudaFuncSetAttribute(qkv_tc_kernel, cudaFuncAttributeMaxDynamicSharedMemorySize,
                         GEMM_SMEM_BYTES);
    cudaFuncSetAttribute(attn_tc_kernel, cudaFuncAttributeMaxDynamicSharedMemorySize,
                         ATT_SMEM_BYTES);

    cvt_er_kernel<<<(2048*D_HEAD/4 + 255)/256, 256>>>(Er);

    dim3 g1(D_MODEL / 128, (BATCH * SEQ) / 128, 3);
    qkv_tc_kernel<<<g1, 256, GEMM_SMEM_BYTES>>>(x, Wq, bq, Wk, bk, Wv, bv);

    dim3 g3(SEQ / 128, BHN);
    attn_tc_kernel<<<g3, 256, ATT_SMEM_BYTES>>>(out);
}

// round 17
// speedup vs baseline: 1.2314x; 1.0271x over previous
#include <cuda_runtime.h>
#include <cuda_fp16.h>
#include <math.h>
#include <stdint.h>

#define D_MODEL 1024
#define NUM_HEADS 16
#define D_HEAD 64
#define BATCH 2
#define SEQ 2048
#define BHN (BATCH*NUM_HEADS)

// -------- scratch (static device memory; no runtime allocation) --------
__device__ float  g_q  [(size_t)BATCH*SEQ*D_MODEL];          // 16 MB fp32
__device__ __half g_k  [(size_t)BATCH*SEQ*D_MODEL];          // 8 MB fp16
__device__ __half g_vT [(size_t)BHN*D_HEAD*SEQ];             // 8 MB fp16, [bh][d][s]
__device__ __half g_erh[(size_t)2240*D_HEAD];                // Er fp16, rows 2048..2239 zero pad

// ---------------- helpers ----------------
__device__ __forceinline__ void mma_f16(float& c0, float& c1, float& c2, float& c3,
                                        uint32_t a0, uint32_t a1, uint32_t a2, uint32_t a3,
                                        uint32_t b0, uint32_t b1) {
    asm volatile(
        "mma.sync.aligned.m16n8k16.row.col.f32.f16.f16.f32 "
        "{%0,%1,%2,%3}, {%4,%5,%6,%7}, {%8,%9}, {%0,%1,%2,%3};"
        : "+f"(c0), "+f"(c1), "+f"(c2), "+f"(c3)
        : "r"(a0), "r"(a1), "r"(a2), "r"(a3), "r"(b0), "r"(b1));
}
__device__ __forceinline__ void ldsm_x4(uint32_t& r0, uint32_t& r1, uint32_t& r2, uint32_t& r3,
                                        uint32_t saddr) {
    asm volatile("ldmatrix.sync.aligned.m8n8.x4.shared.b16 {%0,%1,%2,%3}, [%4];"
                 : "=r"(r0), "=r"(r1), "=r"(r2), "=r"(r3) : "r"(saddr));
}
__device__ __forceinline__ uint32_t pack_h2(float x, float y) {
    __half2 h = __floats2half2_rn(x, y);
    return *(uint32_t*)&h;
}
__device__ __forceinline__ uint32_t exp2_h2(float x, float y) {
    uint32_t u, r;
    asm("cvt.rn.f16x2.f32 %0, %1, %2;" : "=r"(u) : "f"(y), "f"(x));
    asm("ex2.approx.f16x2 %0, %1;" : "=r"(r) : "r"(u));
    return r;
}
__device__ __forceinline__ void cp_async16(uint32_t saddr, const void* g) {
    asm volatile("cp.async.cg.shared.global [%0], [%1], 16;" :: "r"(saddr), "l"(g));
}
#define CP_COMMIT() asm volatile("cp.async.commit_group;")
#define CP_WAIT0()  asm volatile("cp.async.wait_group 0;")

#define ONES_H2 0x3C003C00u
#define SCL 0.18033688011112042f   // 0.125 * log2(e)

#define HP 40
#define GEMM_SMEM_BYTES (2*128*HP*2*2)   // 40960 B

// ============================================================
// Kernel 0: convert Er to fp16 (pad rows stay zero from init).
// ============================================================
__global__ __launch_bounds__(256)
void cvt_er_kernel(const float* __restrict__ Er)
{
    int i = (blockIdx.x * blockDim.x + threadIdx.x) * 4;
    if (i >= 2048 * D_HEAD) return;
    float4 v = *(const float4*)(Er + i);
    *(uint32_t*)(g_erh + i)     = pack_h2(v.x, v.y);
    *(uint32_t*)(g_erh + i + 2) = pack_h2(v.z, v.w);
}

// ============================================================
// Kernel 1 (fp16 tensor core): Q/K/V projection (round-13 form).
// ============================================================
__global__ __launch_bounds__(256, 2)
void qkv_tc_kernel(const float* __restrict__ x,
                   const float* __restrict__ Wq, const float* __restrict__ bq,
                   const float* __restrict__ Wk, const float* __restrict__ bk,
                   const float* __restrict__ Wv, const float* __restrict__ bv)
{
    const float* W; const float* bias;
    if (blockIdx.z == 0)      { W = Wq; bias = bq; }
    else if (blockIdx.z == 1) { W = Wk; bias = bk; }
    else                      { W = Wv; bias = bv; }

    extern __shared__ __half smh[];
    __half* As = smh;                // [2][128][HP]
    __half* Bs = smh + 2*128*HP;     // [2][128][HP]
    const uint32_t As_u = (uint32_t)__cvta_generic_to_shared(As);
    const uint32_t Bs_u = (uint32_t)__cvta_generic_to_shared(Bs);

    const int m0 = blockIdx.y * 128;
    const int n0 = blockIdx.x * 128;
    const int tid = threadIdx.x;
    const int wid = tid >> 5;
    const int lane = tid & 31;
    const int gid = lane >> 2;
    const int tig = lane & 3;
    const int wm = wid >> 2;
    const int wn = wid & 3;

    const int lmA_row = (lane & 7) + ((lane >> 3) & 1) * 8;
    const int lmA_kof = ((lane >> 4) & 1) * 8;
    const int lmB_row = (lane & 7) + ((lane >> 4) & 1) * 8;
    const int lmB_kof = ((lane >> 3) & 1) * 8;

    const float* Ag = x + (size_t)m0 * D_MODEL;
    const float* Bg = W + (size_t)n0 * D_MODEL;

    float c[4][4][4];
#pragma unroll
    for (int mt = 0; mt < 4; mt++)
#pragma unroll
        for (int nt = 0; nt < 4; nt++)
#pragma unroll
            for (int r = 0; r < 4; r++) c[mt][nt][r] = 0.f;

    const int lrow = tid >> 3;
    const int lc4  = (tid & 7) * 4;

    float4 pa[4], pb[4];
#pragma unroll
    for (int i = 0; i < 4; i++) {
        pa[i] = *(const float4*)(Ag + (size_t)(lrow + i*32) * D_MODEL + lc4);
        pb[i] = *(const float4*)(Bg + (size_t)(lrow + i*32) * D_MODEL + lc4);
    }
#pragma unroll
    for (int i = 0; i < 4; i++) {
        __half* da = As + (lrow + i*32) * HP + lc4;
        *(uint32_t*)da       = pack_h2(pa[i].x, pa[i].y);
        *(uint32_t*)(da + 2) = pack_h2(pa[i].z, pa[i].w);
        __half* db = Bs + (lrow + i*32) * HP + lc4;
        *(uint32_t*)db       = pack_h2(pb[i].x, pb[i].y);
        *(uint32_t*)(db + 2) = pack_h2(pb[i].z, pb[i].w);
    }
    __syncthreads();

    for (int k0 = 0; k0 < D_MODEL; k0 += 32) {
        const int buf = (k0 >> 5) & 1;
        const bool has_next = (k0 + 32) < D_MODEL;
        if (has_next) {
#pragma unroll
            for (int i = 0; i < 4; i++) {
                pa[i] = *(const float4*)(Ag + (size_t)(lrow + i*32) * D_MODEL + k0 + 32 + lc4);
                pb[i] = *(const float4*)(Bg + (size_t)(lrow + i*32) * D_MODEL + k0 + 32 + lc4);
            }
        }
#pragma unroll
        for (int ks = 0; ks < 2; ks++) {
            const int kk = ks * 16;
            uint32_t a[4][4];
#pragma unroll
            for (int mt = 0; mt < 4; mt++) {
                const uint32_t addr = As_u +
                    2u * (uint32_t)((buf*128 + wm*64 + mt*16 + lmA_row) * HP + kk + lmA_kof);
                ldsm_x4(a[mt][0], a[mt][1], a[mt][2], a[mt][3], addr);
            }
#pragma unroll
            for (int ntp = 0; ntp < 2; ntp++) {
                uint32_t b00, b01, b10, b11;
                const uint32_t addr = Bs_u +
                    2u * (uint32_t)((buf*128 + wn*32 + ntp*16 + lmB_row) * HP + kk + lmB_kof);
                ldsm_x4(b00, b01, b10, b11, addr);
#pragma unroll
                for (int mt = 0; mt < 4; mt++) {
                    mma_f16(c[mt][2*ntp][0], c[mt][2*ntp][1], c[mt][2*ntp][2], c[mt][2*ntp][3],
                            a[mt][0], a[mt][1], a[mt][2], a[mt][3], b00, b01);
                    mma_f16(c[mt][2*ntp+1][0], c[mt][2*ntp+1][1], c[mt][2*ntp+1][2], c[mt][2*ntp+1][3],
                            a[mt][0], a[mt][1], a[mt][2], a[mt][3], b10, b11);
                }
            }
        }
        if (has_next) {
            const int nb = buf ^ 1;
#pragma unroll
            for (int i = 0; i < 4; i++) {
                __half* da = As + nb*128*HP + (lrow + i*32) * HP + lc4;
                *(uint32_t*)da       = pack_h2(pa[i].x, pa[i].y);
                *(uint32_t*)(da + 2) = pack_h2(pa[i].z, pa[i].w);
                __half* db = Bs + nb*128*HP + (lrow + i*32) * HP + lc4;
                *(uint32_t*)db       = pack_h2(pb[i].x, pb[i].y);
                *(uint32_t*)(db + 2) = pack_h2(pb[i].z, pb[i].w);
            }
            __syncthreads();
        }
    }

    if (blockIdx.z == 0) {
#pragma unroll
        for (int nt = 0; nt < 4; nt++) {
            const int col = n0 + wn*32 + nt*8 + 2*tig;
            const float2 bb = *(const float2*)(bias + col);
#pragma unroll
            for (int mt = 0; mt < 4; mt++) {
                const int row = m0 + wm*64 + mt*16 + gid;
                *(float2*)(g_q + (size_t)row * D_MODEL + col) =
                    make_float2(c[mt][nt][0] + bb.x, c[mt][nt][1] + bb.y);
                *(float2*)(g_q + (size_t)(row + 8) * D_MODEL + col) =
                    make_float2(c[mt][nt][2] + bb.x, c[mt][nt][3] + bb.y);
            }
        }
    } else if (blockIdx.z == 1) {
#pragma unroll
        for (int nt = 0; nt < 4; nt++) {
            const int col = n0 + wn*32 + nt*8 + 2*tig;
            const float2 bb = *(const float2*)(bias + col);
#pragma unroll
            for (int mt = 0; mt < 4; mt++) {
                const int row = m0 + wm*64 + mt*16 + gid;
                *(__half2*)(g_k + (size_t)row * D_MODEL + col) =
                    __floats2half2_rn(c[mt][nt][0] + bb.x, c[mt][nt][1] + bb.y);
                *(__half2*)(g_k + (size_t)(row + 8) * D_MODEL + col) =
                    __floats2half2_rn(c[mt][nt][2] + bb.x, c[mt][nt][3] + bb.y);
            }
        }
    } else {
#pragma unroll
        for (int nt = 0; nt < 4; nt++) {
            const int col = n0 + wn*32 + nt*8 + 2*tig;
            const float2 bb = *(const float2*)(bias + col);
            const int hh = col >> 6;
            const int d0 = col & 63;
#pragma unroll
            for (int mt = 0; mt < 4; mt++) {
                const int row = m0 + wm*64 + mt*16 + gid;
                const int bidx = row >> 11;
                const int sidx = row & 2047;
                __half* base = g_vT + ((size_t)(bidx*NUM_HEADS + hh) * D_HEAD + d0) * SEQ;
                base[sidx]            = __float2half(c[mt][nt][0] + bb.x);
                base[SEQ + sidx]      = __float2half(c[mt][nt][1] + bb.y);
                base[sidx + 8]        = __float2half(c[mt][nt][2] + bb.x);
                base[SEQ + sidx + 8]  = __float2half(c[mt][nt][3] + bb.y);
            }
        }
    }
}

// ============================================================
// Kernel 2: fused flash attention + inline rel-bias GEMM.
// Rel chunk kt+2 computed mid-tile (required ordering: tile kt's
// seeds read chunks kt..kt+2). Ring rows/cols are LANE-private,
// so no barrier is needed between rel-store and seed-load.
// One __syncthreads per tile.
// ============================================================
#define AHP 72
#define RRS 200
#define SM_KS   0
#define SM_VT   (2*64*AHP)
#define SM_ER   (2*(2*64*AHP))
#define SM_REL  (SM_ER + 2*64*AHP)
#define ATT_SMEM_HALVES (SM_REL + 128*RRS)
#define ATT_SMEM_BYTES (ATT_SMEM_HALVES * 2)   // 106,496 B

__global__ __launch_bounds__(256, 2)
void attn_tc_kernel(float* __restrict__ out)
{
    const int qt = gridDim.x - 1 - blockIdx.x;
    const int bh = blockIdx.y;
    const int b = bh >> 4, h = bh & 15;
    const int s0 = qt * 128;
    const int ebase = 1920 - s0;          // Er row base for chunk 0

    extern __shared__ __half smh[];
    __half* rel = smh + SM_REL;           // [128][RRS]

    const int tid = threadIdx.x;
    const int wid = tid >> 5;
    const int lane = tid & 31;
    const int gid = lane >> 2;
    const int tig = lane & 3;
    const int r0 = wid*16 + gid;
    const int r1 = r0 + 8;
    const int sg0 = s0 + r0;
    const int sg1 = s0 + r1;

    const int lmB_row = (lane & 7) + ((lane >> 4) & 1) * 8;
    const int lmB_kof = ((lane >> 3) & 1) * 8;

    const float*  qb  = g_q + ((size_t)b * SEQ + s0) * D_MODEL + (size_t)h * D_HEAD;
    const __half* kb  = g_k + (size_t)b * SEQ * D_MODEL + (size_t)h * D_HEAD;
    const __half* vtb = g_vT + (size_t)bh * D_HEAD * SEQ;

    // Q fragments resident in registers
    uint32_t qf[4][4];
#pragma unroll
    for (int k4 = 0; k4 < 4; k4++) {
        const int cc = k4*16 + 2*tig;
        const float2 x0 = *(const float2*)(qb + (size_t)r0 * D_MODEL + cc);
        const float2 x1 = *(const float2*)(qb + (size_t)r1 * D_MODEL + cc);
        const float2 x2 = *(const float2*)(qb + (size_t)r0 * D_MODEL + cc + 8);
        const float2 x3 = *(const float2*)(qb + (size_t)r1 * D_MODEL + cc + 8);
        qf[k4][0] = pack_h2(x0.x, x0.y);
        qf[k4][1] = pack_h2(x1.x, x1.y);
        qf[k4][2] = pack_h2(x2.x, x2.y);
        qf[k4][3] = pack_h2(x3.x, x3.y);
    }

    const uint32_t ks_u = (uint32_t)__cvta_generic_to_shared(smh + SM_KS);
    const uint32_t vt_u = (uint32_t)__cvta_generic_to_shared(smh + SM_VT);
    const uint32_t er_u = (uint32_t)__cvta_generic_to_shared(smh + SM_ER);
    const int ci0 = tid * 2;
    const int ci1 = tid * 2 + 1;
    const int krow0 = ci0 >> 3, ko0 = (ci0 & 7) * 8;
    const int krow1 = ci1 >> 3, ko1 = (ci1 & 7) * 8;

    float o[8][4];
#pragma unroll
    for (int nt = 0; nt < 8; nt++) { o[nt][0]=0.f; o[nt][1]=0.f; o[nt][2]=0.f; o[nt][3]=0.f; }
    float lacc[4] = {0.f, 0.f, 0.f, 0.f};
    float m0v = -1e30f, m1v = -1e30f;
    const int nkt = 2 * qt + 2;
    const bool rodd = (r0 & 1);

    // prologue: K/V tile0 + Er chunks 0,1; compute rel chunks 0,1
    {
        cp_async16(ks_u + (krow0*AHP + ko0)*2, kb + (size_t)krow0 * D_MODEL + ko0);
        cp_async16(ks_u + (krow1*AHP + ko1)*2, kb + (size_t)krow1 * D_MODEL + ko1);
        cp_async16(vt_u + (krow0*AHP + ko0)*2, vtb + (size_t)krow0 * SEQ + ko0);
        cp_async16(vt_u + (krow1*AHP + ko1)*2, vtb + (size_t)krow1 * SEQ + ko1);
#pragma unroll
        for (int cc = 0; cc < 2; cc++) {
            const uint32_t soff = (uint32_t)(cc * 64 * AHP * 2);
            const __half* esrc = g_erh + (size_t)(ebase + 64*cc) * D_HEAD;
            cp_async16(er_u + soff + (krow0*AHP + ko0)*2, esrc + (size_t)krow0 * D_HEAD + ko0);
            cp_async16(er_u + soff + (krow1*AHP + ko1)*2, esrc + (size_t)krow1 * D_HEAD + ko1);
        }
        CP_COMMIT();
        CP_WAIT0();
        __syncthreads();

#pragma unroll
        for (int cc = 0; cc < 2; cc++) {
            const uint32_t erb = er_u + (uint32_t)(cc * 64 * AHP * 2);
#pragma unroll
            for (int ntp = 0; ntp < 4; ntp++) {
                float ra[4] = {0,0,0,0}, rb[4] = {0,0,0,0};
#pragma unroll
                for (int k4 = 0; k4 < 4; k4++) {
                    const int kk = k4 * 16;
                    uint32_t b00, b01, b10, b11;
                    ldsm_x4(b00, b01, b10, b11,
                            erb + 2u*(uint32_t)((ntp*16 + lmB_row)*AHP + kk + lmB_kof));
                    mma_f16(ra[0], ra[1], ra[2], ra[3],
                            qf[k4][0], qf[k4][1], qf[k4][2], qf[k4][3], b00, b01);
                    mma_f16(rb[0], rb[1], rb[2], rb[3],
                            qf[k4][0], qf[k4][1], qf[k4][2], qf[k4][3], b10, b11);
                }
                const int i0 = ntp*16 + 2*tig;
#pragma unroll
                for (int hh2 = 0; hh2 < 4; hh2++) {
                    const int rr = (hh2 & 1) ? r1 : r0;
                    const int ii = i0 + (hh2 >> 1) * 8;
                    const float v0 = (hh2 == 0) ? ra[0] : (hh2 == 1) ? ra[2] : (hh2 == 2) ? rb[0] : rb[2];
                    const float v1 = (hh2 == 0) ? ra[1] : (hh2 == 1) ? ra[3] : (hh2 == 2) ? rb[1] : rb[3];
                    const int tw = 64*cc + ii + rr - 127;
                    __half* rp = rel + rr * RRS;
                    if (!rodd) {
                        if (tw >= 0)     rp[tw]     = __float2half(v0);
                        if (tw + 1 >= 0) rp[tw + 1] = __float2half(v1);
                    } else {
                        if (tw >= 0) *(uint32_t*)(rp + tw) = pack_h2(v0, v1);
                    }
                }
            }
        }
        __syncthreads();                 // Er slot 0 free for reuse
        const __half* esrc = g_erh + (size_t)(ebase + 128) * D_HEAD;
        cp_async16(er_u + (krow0*AHP + ko0)*2, esrc + (size_t)krow0 * D_HEAD + ko0);
        cp_async16(er_u + (krow1*AHP + ko1)*2, esrc + (size_t)krow1 * D_HEAD + ko1);
        CP_COMMIT();
    }

    int rbase = 0;   // (64*kt) % 192

    for (int kt = 0; kt < nkt; kt++) {
        const int t0 = kt * 64;
        const int buf = kt & 1;
        const bool masked = (kt >= 2*qt);

        CP_WAIT0();
        __syncthreads();                 // K/V(kt), Er(kt+2) ready

        if (kt + 1 < nkt) {
            const int t0n = t0 + 64;
            const int boff = (buf ^ 1) * 64 * AHP * 2;
            cp_async16(ks_u + boff + (krow0*AHP + ko0)*2, kb + (size_t)(t0n + krow0) * D_MODEL + ko0);
            cp_async16(ks_u + boff + (krow1*AHP + ko1)*2, kb + (size_t)(t0n + krow1) * D_MODEL + ko1);
            cp_async16(vt_u + boff + (krow0*AHP + ko0)*2, vtb + (size_t)krow0 * SEQ + t0n + ko0);
            cp_async16(vt_u + boff + (krow1*AHP + ko1)*2, vtb + (size_t)krow1 * SEQ + t0n + ko1);
            const uint32_t eoff = (uint32_t)(((kt + 3) & 1) * 64 * AHP * 2);
            const __half* esrc = g_erh + (size_t)(ebase + 64*(kt + 3)) * D_HEAD;
            cp_async16(er_u + eoff + (krow0*AHP + ko0)*2, esrc + (size_t)krow0 * D_HEAD + ko0);
            cp_async16(er_u + eoff + (krow1*AHP + ko1)*2, esrc + (size_t)krow1 * D_HEAD + ko1);
        }
        CP_COMMIT();

        // ---- rel chunk kt+2 (only if some tile consumes unmasked data) ----
        // Ring cells are lane-private: no barrier needed before seeds.
        if (kt + 2 < nkt) {
            const uint32_t erb = er_u + (uint32_t)((kt & 1) * 64 * AHP * 2);
#pragma unroll
            for (int ntp = 0; ntp < 4; ntp++) {
                float ra[4] = {0,0,0,0}, rb[4] = {0,0,0,0};
#pragma unroll
                for (int k4 = 0; k4 < 4; k4++) {
                    const int kk = k4 * 16;
                    uint32_t b00, b01, b10, b11;
                    ldsm_x4(b00, b01, b10, b11,
                            erb + 2u*(uint32_t)((ntp*16 + lmB_row)*AHP + kk + lmB_kof));
                    mma_f16(ra[0], ra[1], ra[2], ra[3],
                            qf[k4][0], qf[k4][1], qf[k4][2], qf[k4][3], b00, b01);
                    mma_f16(rb[0], rb[1], rb[2], rb[3],
                            qf[k4][0], qf[k4][1], qf[k4][2], qf[k4][3], b10, b11);
                }
                const int i0 = ntp*16 + 2*tig;
#pragma unroll
                for (int hh2 = 0; hh2 < 4; hh2++) {
                    const int rr = (hh2 & 1) ? r1 : r0;
                    const int ii = i0 + (hh2 >> 1) * 8;
                    const float v0 = (hh2 == 0) ? ra[0] : (hh2 == 1) ? ra[2] : (hh2 == 2) ? rb[0] : rb[2];
                    const float v1 = (hh2 == 0) ? ra[1] : (hh2 == 1) ? ra[3] : (hh2 == 2) ? rb[1] : rb[3];
                    int idx = rbase + ii + rr + 1;
                    if (idx >= 192) idx -= 192;
                    __half* rp = rel + rr * RRS;
                    if (!rodd) {
                        int idx2 = idx + 1; if (idx2 >= 192) idx2 = 0;
                        rp[idx]  = __float2half(v0);
                        rp[idx2] = __float2half(v1);
                    } else {
                        *(uint32_t*)(rp + idx) = pack_h2(v0, v1);
                    }
                }
            }
        }

        // ---- seed s_ from skewed ring (lane-private cells, aligned u32) ----
        float s_[8][4];
        {
            const __half* rp0 = rel + r0 * RRS;
            const __half* rp1 = rel + r1 * RRS;
#pragma unroll
            for (int nt = 0; nt < 8; nt++) {
                const int ridx = rbase + nt*8 + 2*tig;
                const uint32_t u0 = *(const uint32_t*)(rp0 + ridx);
                const uint32_t u1 = *(const uint32_t*)(rp1 + ridx);
                const float2 f0 = __half22float2(*(const __half2*)&u0);
                const float2 f1 = __half22float2(*(const __half2*)&u1);
                s_[nt][0] = f0.x; s_[nt][1] = f0.y;
                s_[nt][2] = f1.x; s_[nt][3] = f1.y;
            }
        }

        const uint32_t ksb_u = ks_u + (uint32_t)(buf * 64 * AHP * 2);
        const uint32_t vtf_u = vt_u + (uint32_t)(buf * 64 * AHP * 2);

        // S += Q K^T
#pragma unroll
        for (int k4 = 0; k4 < 4; k4++) {
            const int kk = k4 * 16;
#pragma unroll
            for (int ntp = 0; ntp < 4; ntp++) {
                uint32_t b00, b01, b10, b11;
                const uint32_t addr = ksb_u +
                    2u * (uint32_t)((ntp*16 + lmB_row) * AHP + kk + lmB_kof);
                ldsm_x4(b00, b01, b10, b11, addr);
                mma_f16(s_[2*ntp][0], s_[2*ntp][1], s_[2*ntp][2], s_[2*ntp][3],
                        qf[k4][0], qf[k4][1], qf[k4][2], qf[k4][3], b00, b01);
                mma_f16(s_[2*ntp+1][0], s_[2*ntp+1][1], s_[2*ntp+1][2], s_[2*ntp+1][3],
                        qf[k4][0], qf[k4][1], qf[k4][2], qf[k4][3], b10, b11);
            }
        }

        // ---- online softmax (log2 domain), row half 0 ----
        {
            float rmax = -1e30f;
            if (masked) {
#pragma unroll
                for (int nt = 0; nt < 8; nt++) {
                    int tc = t0 + nt*8 + 2*tig;
                    float v0 = s_[nt][0] * SCL;
                    float v1 = s_[nt][1] * SCL;
                    v0 = (tc     <= sg0) ? v0 : -1e30f;
                    v1 = (tc + 1 <= sg0) ? v1 : -1e30f;
                    s_[nt][0] = v0; s_[nt][1] = v1;
                    rmax = fmaxf(rmax, fmaxf(v0, v1));
                }
            } else {
#pragma unroll
                for (int nt = 0; nt < 8; nt++) {
                    float v0 = s_[nt][0] * SCL;
                    float v1 = s_[nt][1] * SCL;
                    s_[nt][0] = v0; s_[nt][1] = v1;
                    rmax = fmaxf(rmax, fmaxf(v0, v1));
                }
            }
            rmax = fmaxf(rmax, __shfl_xor_sync(0xffffffffu, rmax, 1));
            rmax = fmaxf(rmax, __shfl_xor_sync(0xffffffffu, rmax, 2));
            float mn = fmaxf(m0v, rmax);
            float alpha = exp2f(m0v - mn);
            m0v = mn;
            lacc[0] *= alpha;
#pragma unroll
            for (int nt = 0; nt < 8; nt++) {
                s_[nt][0] = __uint_as_float(exp2_h2(s_[nt][0] - mn, s_[nt][1] - mn));
                o[nt][0] *= alpha; o[nt][1] *= alpha;
            }
        }
        // ---- row half 1 ----
        {
            float rmax = -1e30f;
            if (masked) {
#pragma unroll
                for (int nt = 0; nt < 8; nt++) {
                    int tc = t0 + nt*8 + 2*tig;
                    float v0 = s_[nt][2] * SCL;
                    float v1 = s_[nt][3] * SCL;
                    v0 = (tc     <= sg1) ? v0 : -1e30f;
                    v1 = (tc + 1 <= sg1) ? v1 : -1e30f;
                    s_[nt][2] = v0; s_[nt][3] = v1;
                    rmax = fmaxf(rmax, fmaxf(v0, v1));
                }
            } else {
#pragma unroll
                for (int nt = 0; nt < 8; nt++) {
                    float v0 = s_[nt][2] * SCL;
                    float v1 = s_[nt][3] * SCL;
                    s_[nt][2] = v0; s_[nt][3] = v1;
                    rmax = fmaxf(rmax, fmaxf(v0, v1));
                }
            }
            rmax = fmaxf(rmax, __shfl_xor_sync(0xffffffffu, rmax, 1));
            rmax = fmaxf(rmax, __shfl_xor_sync(0xffffffffu, rmax, 2));
            float mn = fmaxf(m1v, rmax);
            float alpha = exp2f(m1v - mn);
            m1v = mn;
            lacc[2] *= alpha;
#pragma unroll
            for (int nt = 0; nt < 8; nt++) {
                s_[nt][2] = __uint_as_float(exp2_h2(s_[nt][2] - mn, s_[nt][3] - mn));
                o[nt][2] *= alpha; o[nt][3] *= alpha;
            }
        }

        // O += P V ; l += P 1
#pragma unroll
        for (int k4 = 0; k4 < 4; k4++) {
            const int kk = k4 * 16;
            const uint32_t a0 = __float_as_uint(s_[2*k4][0]);
            const uint32_t a1 = __float_as_uint(s_[2*k4][2]);
            const uint32_t a2 = __float_as_uint(s_[2*k4+1][0]);
            const uint32_t a3 = __float_as_uint(s_[2*k4+1][2]);
#pragma unroll
            for (int ntp = 0; ntp < 4; ntp++) {
                uint32_t b00, b01, b10, b11;
                const uint32_t addr = vtf_u +
                    2u * (uint32_t)((ntp*16 + lmB_row) * AHP + kk + lmB_kof);
                ldsm_x4(b00, b01, b10, b11, addr);
                mma_f16(o[2*ntp][0], o[2*ntp][1], o[2*ntp][2], o[2*ntp][3],
                        a0, a1, a2, a3, b00, b01);
                mma_f16(o[2*ntp+1][0], o[2*ntp+1][1], o[2*ntp+1][2], o[2*ntp+1][3],
                        a0, a1, a2, a3, b10, b11);
            }
            mma_f16(lacc[0], lacc[1], lacc[2], lacc[3],
                    a0, a1, a2, a3, ONES_H2, ONES_H2);
        }

        rbase += 64;
        if (rbase >= 192) rbase = 0;
    }

    const float inv0 = 1.f / lacc[0];
    const float inv1 = 1.f / lacc[2];
    float* ob = out + (size_t)b * SEQ * D_MODEL + (size_t)h * D_HEAD;
#pragma unroll
    for (int nt = 0; nt < 8; nt++) {
        const int d = nt*8 + 2*tig;
        *(float2*)(ob + (size_t)sg0 * D_MODEL + d) = make_float2(o[nt][0]*inv0, o[nt][1]*inv0);
        *(float2*)(ob + (size_t)sg1 * D_MODEL + d) = make_float2(o[nt][2]*inv1, o[nt][3]*inv1);
    }
}

// ============================================================
// launcher
// ============================================================
extern "C" void kernel_launch(void* const* d_in, const int* in_sizes, int n_in,
                              void* d_out, int out_size)
{
    const float* x  = (const float*)d_in[0];
    const float* Wq = (const float*)d_in[1];
    const float* bq = (const float*)d_in[2];
    const float* Wk = (const float*)d_in[3];
    const float* bk = (const float*)d_in[4];
    const float* Wv = (const float*)d_in[5];
    const float* bv = (const float*)d_in[6];
    const float* Er = (const float*)d_in[7];
    float* out = (float*)d_out;

    cudaFuncSetAttribute(qkv_tc_kernel, cudaFuncAttributeMaxDynamicSharedMemorySize,
                         GEMM_SMEM_BYTES);
    cudaFuncSetAttribute(attn_tc_kernel, cudaFuncAttributeMaxDynamicSharedMemorySize,
                         ATT_SMEM_BYTES);

    cvt_er_kernel<<<(2048*D_HEAD/4 + 255)/256, 256>>>(Er);

    dim3 g1(D_MODEL / 128, (BATCH * SEQ) / 128, 3);
    qkv_tc_kernel<<<g1, 256, GEMM_SMEM_BYTES>>>(x, Wq, bq, Wk, bk, Wv, bv);

    dim3 g3(SEQ / 128, BHN);
    attn_tc_kernel<<<g3, 256, ATT_SMEM_BYTES>>>(out);
}